// round 2
// baseline (speedup 1.0000x reference)
#include <cuda_runtime.h>
#include <cuda_bf16.h>
#include <math.h>

#define NSEG 17        // labels 0..16
#define NB   16        // batch
#define TPB  256
#define SIGMA_DIS 3.0f

// Global accumulators (scratch; no allocations allowed)
__device__ float        g_ss[NB * NSEG];
__device__ unsigned int g_cnt[NB * NSEG];

__global__ void zero_acc_kernel() {
    int t = blockIdx.x * blockDim.x + threadIdx.x;
    if (t < NB * NSEG) {
        g_ss[t]  = 0.0f;
        g_cnt[t] = 0u;
    }
}

// Stage A: per-pixel squared norm -> per-(batch,label) sum + count.
// Per-thread privatized shared accumulators: s[label*TPB + tid] is
// bank-conflict-free across a warp for any label pattern.
__global__ void __launch_bounds__(TPB) segsum_kernel(
    const float* __restrict__ pred,   // (B, 4, P)
    const int*   __restrict__ lab,    // (B, P)
    int P)
{
    __shared__ float s_ss [NSEG * TPB];
    __shared__ int   s_cnt[NSEG * TPB];

    const int t = threadIdx.x;
    const int b = blockIdx.y;

    #pragma unroll
    for (int k = 0; k < NSEG; k++) {
        s_ss [k * TPB + t] = 0.0f;
        s_cnt[k * TPB + t] = 0;
    }
    __syncthreads();

    const float* p0 = pred + (size_t)b * 4 * P;
    const int*   l0 = lab  + (size_t)b * P;

    const int stride = gridDim.x * TPB * 4;
    for (int base = (blockIdx.x * TPB + t) * 4; base + 3 < P; base += stride) {
        int4   lv = *reinterpret_cast<const int4*>(l0 + base);
        float4 c0 = *reinterpret_cast<const float4*>(p0 + base);
        float4 c1 = *reinterpret_cast<const float4*>(p0 + (size_t)P     + base);
        float4 c2 = *reinterpret_cast<const float4*>(p0 + (size_t)2 * P + base);
        float4 c3 = *reinterpret_cast<const float4*>(p0 + (size_t)3 * P + base);

        float sq0 = c0.x * c0.x + c1.x * c1.x + c2.x * c2.x + c3.x * c3.x;
        float sq1 = c0.y * c0.y + c1.y * c1.y + c2.y * c2.y + c3.y * c3.y;
        float sq2 = c0.z * c0.z + c1.z * c1.z + c2.z * c2.z + c3.z * c3.z;
        float sq3 = c0.w * c0.w + c1.w * c1.w + c2.w * c2.w + c3.w * c3.w;

        s_ss [lv.x * TPB + t] += sq0;  s_cnt[lv.x * TPB + t] += 1;
        s_ss [lv.y * TPB + t] += sq1;  s_cnt[lv.y * TPB + t] += 1;
        s_ss [lv.z * TPB + t] += sq2;  s_cnt[lv.z * TPB + t] += 1;
        s_ss [lv.w * TPB + t] += sq3;  s_cnt[lv.w * TPB + t] += 1;
    }
    __syncthreads();

    // Tree-reduce the 256 per-thread partials for each of the 17 bins.
    for (int off = TPB / 2; off >= 1; off >>= 1) {
        if (t < off) {
            #pragma unroll
            for (int k = 0; k < NSEG; k++) {
                s_ss [k * TPB + t] += s_ss [k * TPB + t + off];
                s_cnt[k * TPB + t] += s_cnt[k * TPB + t + off];
            }
        }
        __syncthreads();
    }

    if (t < NSEG) {
        atomicAdd(&g_ss [b * NSEG + t], s_ss [t * TPB]);
        atomicAdd(&g_cnt[b * NSEG + t], (unsigned int)s_cnt[t * TPB]);
    }
}

// Stage B: tiny pairwise epilogue, one thread per batch, warp-reduce sum.
__global__ void loss_kernel(float* __restrict__ out) {
    int b = threadIdx.x;  // 0..31
    float loss = 0.0f;
    if (b < NB) {
        float        m[NSEG];
        unsigned int c[NSEG];
        int nk = 0;
        #pragma unroll
        for (int k = 0; k < NSEG; k++) {
            c[k] = g_cnt[b * NSEG + k];
            if (c[k] > 0u) nk = k;               // max present label
            float cf = (float)c[k];
            m[k] = (c[k] > 0u) ? g_ss[b * NSEG + k] / (cf * cf) : 0.0f;
        }
        float ps = 0.0f;
        for (int i = 1; i < NSEG; i++) {
            if (c[i] == 0u) continue;
            for (int j = i + 1; j < NSEG; j++) {
                if (c[j] == 0u) continue;
                float d = sqrtf(m[i] + m[j]);
                float u = SIGMA_DIS - d;
                ps += log1pf(u * u);
            }
        }
        if (nk > 1) {
            float denom = (float)(nk * (nk - 1));
            loss = ps / fmaxf(denom, 1.0f);
        }
    }
    #pragma unroll
    for (int o = 16; o >= 1; o >>= 1)
        loss += __shfl_down_sync(0xffffffffu, loss, o);
    if (b == 0) out[0] = loss;
}

extern "C" void kernel_launch(void* const* d_in, const int* in_sizes, int n_in,
                              void* d_out, int out_size) {
    const float* pred = (const float*)d_in[0];   // (16, 4, 640, 640) f32
    const int*   lab  = (const int*)d_in[1];     // (16, 640, 640) i32
    float*       out  = (float*)d_out;

    const int P = in_sizes[1] / NB;              // pixels per image = 409600

    zero_acc_kernel<<<1, 512>>>();

    dim3 grid(50, NB);                           // 50*256*4 = 51200 px/sweep, 8 sweeps
    segsum_kernel<<<grid, TPB>>>(pred, lab, P);

    loss_kernel<<<1, 32>>>(out);
}

// round 3
// speedup vs baseline: 1.6031x; 1.6031x over previous
#include <cuda_runtime.h>
#include <cuda_bf16.h>
#include <math.h>

#define NSEG 17          // labels 0..16 (bin 0 = background, excluded from loss)
#define NB   16          // batch
#define TPB  256
#define GX   50          // blocks per batch image
#define NBLK (GX * NB)   // 800 total blocks
#define SIGMA_DIS 3.0f

// Persistent scratch (module-load zeroed; last block restores zeros each call)
__device__ float        g_ss[NB * NSEG];
__device__ float        g_cn[NB * NSEG];
__device__ unsigned int g_done;

__global__ void __launch_bounds__(TPB) fused_discrim_kernel(
    const float* __restrict__ pred,   // (B, 4, P) f32
    const int*   __restrict__ lab,    // (B, P) i32
    int P,
    float* __restrict__ out)
{
    // Per-thread privatized bins: s[k*TPB + t] = {sum_sq, count}
    __shared__ float2 s[NSEG * TPB];
    __shared__ float  s_red[TPB / 32];
    __shared__ int    s_last;

    const int t = threadIdx.x;
    const int b = blockIdx.y;

    #pragma unroll
    for (int k = 0; k < NSEG; k++)
        s[k * TPB + t] = make_float2(0.0f, 0.0f);
    __syncthreads();

    const float* p0 = pred + (size_t)b * 4 * P;
    const int*   l0 = lab  + (size_t)b * P;

    const int stride = GX * TPB * 4;
    #pragma unroll 2
    for (int base = (blockIdx.x * TPB + t) * 4; base + 3 < P; base += stride) {
        int4   lv = *reinterpret_cast<const int4*>(l0 + base);
        float4 c0 = *reinterpret_cast<const float4*>(p0 + base);
        float4 c1 = *reinterpret_cast<const float4*>(p0 + (size_t)P     + base);
        float4 c2 = *reinterpret_cast<const float4*>(p0 + (size_t)2 * P + base);
        float4 c3 = *reinterpret_cast<const float4*>(p0 + (size_t)3 * P + base);

        float sq0 = c0.x * c0.x + c1.x * c1.x + c2.x * c2.x + c3.x * c3.x;
        float sq1 = c0.y * c0.y + c1.y * c1.y + c2.y * c2.y + c3.y * c3.y;
        float sq2 = c0.z * c0.z + c1.z * c1.z + c2.z * c2.z + c3.z * c3.z;
        float sq3 = c0.w * c0.w + c1.w * c1.w + c2.w * c2.w + c3.w * c3.w;

        float2 v;
        v = s[lv.x * TPB + t]; v.x += sq0; v.y += 1.0f; s[lv.x * TPB + t] = v;
        v = s[lv.y * TPB + t]; v.x += sq1; v.y += 1.0f; s[lv.y * TPB + t] = v;
        v = s[lv.z * TPB + t]; v.x += sq2; v.y += 1.0f; s[lv.z * TPB + t] = v;
        v = s[lv.w * TPB + t]; v.x += sq3; v.y += 1.0f; s[lv.w * TPB + t] = v;
    }
    __syncthreads();

    // Tree-reduce 256 per-thread partials for bins 1..16 (bin 0 never used).
    for (int off = TPB / 2; off >= 1; off >>= 1) {
        if (t < off) {
            #pragma unroll
            for (int k = 1; k < NSEG; k++) {
                float2 a = s[k * TPB + t];
                float2 c = s[k * TPB + t + off];
                a.x += c.x; a.y += c.y;
                s[k * TPB + t] = a;
            }
        }
        __syncthreads();
    }

    if (t >= 1 && t < NSEG) {
        atomicAdd(&g_ss[b * NSEG + t], s[t * TPB].x);
        atomicAdd(&g_cn[b * NSEG + t], s[t * TPB].y);
    }

    // Last-block election
    if (t == 0) {
        __threadfence();
        unsigned int old = atomicAdd(&g_done, 1u);
        s_last = (old == (unsigned int)(NBLK - 1)) ? 1 : 0;
    }
    __syncthreads();
    if (!s_last) return;
    __threadfence();

    // ---- Epilogue (only the last block reaches here) ----
    // Load m = SS/c^2 and counts into smem: entry (bb, k) -> s[bb*16 + (k-1)]
    if (t < NB * 16) {
        int bb = t >> 4;
        int k  = (t & 15) + 1;
        float c = g_cn[bb * NSEG + k];
        float m = (c > 0.0f) ? g_ss[bb * NSEG + k] / (c * c) : 0.0f;
        s[t] = make_float2(m, c);
    }
    __syncthreads();

    // Thread t handles row i=(t&15)+1 of batch bb=t>>4: pairs (i, j>i).
    float acc = 0.0f;
    {
        int bb = t >> 4;
        int i  = (t & 15) + 1;
        int nk = 0;
        #pragma unroll
        for (int k = 1; k < NSEG; k++)
            if (s[bb * 16 + k - 1].y > 0.0f) nk = k;
        float2 vi = s[bb * 16 + i - 1];
        if (nk > 1 && vi.y > 0.0f) {
            float inv = 1.0f / fmaxf((float)(nk * (nk - 1)), 1.0f);
            float mi = vi.x;
            for (int j = i + 1; j < NSEG; j++) {
                float2 vj = s[bb * 16 + j - 1];
                if (vj.y > 0.0f) {
                    float d = sqrtf(mi + vj.x);
                    float u = SIGMA_DIS - d;
                    acc += log1pf(u * u) * inv;
                }
            }
        }
    }
    // Block-reduce 256 partial sums
    #pragma unroll
    for (int o = 16; o >= 1; o >>= 1)
        acc += __shfl_down_sync(0xffffffffu, acc, o);
    if ((t & 31) == 0) s_red[t >> 5] = acc;
    __syncthreads();
    if (t == 0) {
        float L = 0.0f;
        #pragma unroll
        for (int w = 0; w < TPB / 32; w++) L += s_red[w];
        out[0] = L;
    }

    // Reset scratch for the next graph replay (restore all-zeros invariant).
    if (t < NB * NSEG) {
        g_ss[t] = 0.0f;
        g_cn[t] = 0.0f;
    }
    if (t == 0) g_done = 0u;
}

extern "C" void kernel_launch(void* const* d_in, const int* in_sizes, int n_in,
                              void* d_out, int out_size) {
    const float* pred = (const float*)d_in[0];   // (16, 4, 640, 640) f32
    const int*   lab  = (const int*)d_in[1];     // (16, 640, 640) i32
    float*       out  = (float*)d_out;

    const int P = in_sizes[1] / NB;              // 409600 pixels per image

    dim3 grid(GX, NB);
    fused_discrim_kernel<<<grid, TPB>>>(pred, lab, P, out);
}